// round 4
// baseline (speedup 1.0000x reference)
#include <cuda_runtime.h>
#include <cuda_bf16.h>
#include <cuda_fp8.h>
#include <cstdint>

#define BPAIRS 4096
#define NROWS  8192
#define DCOLS  256

// tile config: 128x128 output tile, full K=256 fp8 staged once
#define TM 128
#define TN 128
#define SKB 272                 // padded row stride bytes (odd multiple of 16)
#define TILEB (TM * SKB)        // 34816 B per operand
#define SMEM_TOTAL (2 * TILEB)  // 69632 B

#define QSCALE 16.0f            // pre-quant scale; g_fp8 = 256 * g_true
#define INV_GS (4.0f / 256.0f)  // exp arg: 4*g_true - 4 = g_fp8*INV_GS - 4

__device__ __align__(16) uint8_t g_X[NROWS * DCOLS];   // e4m3, scaled by 16
__device__ float g_acc[2];

__device__ __forceinline__ uint32_t smem_u32(const void* p) {
    uint32_t a;
    asm("{ .reg .u64 t; cvta.to.shared.u64 t, %1; cvt.u32.u64 %0, t; }" : "=r"(a) : "l"(p));
    return a;
}
__device__ __forceinline__ void qmma(float d[4], const uint32_t a[4], const uint32_t b0, const uint32_t b1) {
    asm volatile(
        "mma.sync.aligned.m16n8k32.row.col.f32.e4m3.e4m3.f32 "
        "{%0,%1,%2,%3}, {%4,%5,%6,%7}, {%8,%9}, {%0,%1,%2,%3};\n"
        : "+f"(d[0]), "+f"(d[1]), "+f"(d[2]), "+f"(d[3])
        : "r"(a[0]), "r"(a[1]), "r"(a[2]), "r"(a[3]), "r"(b0), "r"(b1));
}
__device__ __forceinline__ void ldsm4(uint32_t r[4], uint32_t addr) {
    asm volatile("ldmatrix.sync.aligned.m8n8.x4.shared.b16 {%0,%1,%2,%3}, [%4];"
                 : "=r"(r[0]), "=r"(r[1]), "=r"(r[2]), "=r"(r[3]) : "r"(addr));
}
__device__ __forceinline__ void cpasync16(uint32_t dst, const void* src) {
    asm volatile("cp.async.cg.shared.global [%0], [%1], 16;" :: "r"(dst), "l"(src));
}

__global__ void k_zero() { g_acc[0] = 0.0f; g_acc[1] = 0.0f; }

// normalize (fp32), accumulate align term, emit e4m3 rows scaled by 16
__global__ void k_norm(const float* __restrict__ A, const float* __restrict__ B) {
    int r = blockIdx.x;
    int t = threadIdx.x;           // 256 == DCOLS
    float a = A[r * DCOLS + t];
    float b = B[r * DCOLS + t];
    float sa = a * a, sb = b * b;
    #pragma unroll
    for (int o = 16; o; o >>= 1) {
        sa += __shfl_xor_sync(0xffffffffu, sa, o);
        sb += __shfl_xor_sync(0xffffffffu, sb, o);
    }
    __shared__ float ssa[8], ssb[8], sdd[8];
    int wid = t >> 5, lane = t & 31;
    if (lane == 0) { ssa[wid] = sa; ssb[wid] = sb; }
    __syncthreads();
    float na = 0.f, nb = 0.f;
    #pragma unroll
    for (int i = 0; i < 8; i++) { na += ssa[i]; nb += ssb[i]; }
    na = fmaxf(sqrtf(na), 1e-12f);
    nb = fmaxf(sqrtf(nb), 1e-12f);
    float an = a / na, bn = b / nb;
    g_X[r * DCOLS + t] =
        (uint8_t)__nv_cvt_float_to_fp8(an * QSCALE, __NV_SATFINITE, __NV_E4M3);
    g_X[(BPAIRS + r) * DCOLS + t] =
        (uint8_t)__nv_cvt_float_to_fp8(bn * QSCALE, __NV_SATFINITE, __NV_E4M3);
    float d = an - bn;
    float dd = d * d;
    #pragma unroll
    for (int o = 16; o; o >>= 1) dd += __shfl_xor_sync(0xffffffffu, dd, o);
    if (lane == 0) sdd[wid] = dd;
    __syncthreads();
    if (t == 0) {
        float s = 0.f;
        #pragma unroll
        for (int i = 0; i < 8; i++) s += sdd[i];
        atomicAdd(&g_acc[0], s);
    }
}

// fp8 Gram over upper-triangular block grid (bj >= bi), 128x128 tiles.
// Full K=256 staged once per tile; ldmatrix.b16-as-fp8 fragments; m16n8k32 QMMA.
__global__ __launch_bounds__(256, 2) void k_gram() {
    extern __shared__ __align__(128) char smem[];
    __shared__ float sred[8];
    uint32_t sb = smem_u32(smem);

    int tid = threadIdx.x;
    int wid = tid >> 5, lane = tid & 31;
    int wm = wid >> 1, wn = wid & 1;
    int m0 = wm * 32, n0 = wn * 64;

    // decode (bi, bj), bj >= bi over 64x64 tile grid
    int bi = 0, rem = blockIdx.x, rowlen = NROWS / TM;
    while (rem >= rowlen) { rem -= rowlen; bi++; rowlen--; }
    int bj = bi + rem;
    int ai0 = bi * TM, bj0 = bj * TN;

    // stage A and B tiles: 128 rows x 256 B, 16B vectors, 2048 chunks each
    {
        const uint8_t* ga = &g_X[(size_t)ai0 * DCOLS];
        const uint8_t* gb = &g_X[(size_t)bj0 * DCOLS];
        #pragma unroll
        for (int i = 0; i < 8; i++) {
            int idx = tid + i * 256;            // 0..2047
            int r = idx >> 4, u = idx & 15;
            cpasync16(sb + r * SKB + u * 16, ga + (size_t)r * DCOLS + u * 16);
            cpasync16(sb + TILEB + r * SKB + u * 16, gb + (size_t)r * DCOLS + u * 16);
        }
        asm volatile("cp.async.commit_group;" ::: "memory");
        asm volatile("cp.async.wait_group 0;" ::: "memory");
    }
    __syncthreads();

    // per-lane fragment base offsets
    // A (m16k32 via ldmatrix.x4 over 16B-wide rows): lanes 0-15 rows, 16-31 rows @+16B
    uint32_t a_off = (uint32_t)((m0 + (lane & 15)) * SKB + ((lane >> 4) << 4));
    // B: m0:n0-7@k0-15, m1:n0-7@k16-31, m2:n8-15@k0-15, m3:n8-15@k16-31
    int bcol = (lane & 7) + ((lane >> 4) << 3);
    uint32_t b_off = (uint32_t)((n0 + bcol) * SKB + ((lane & 8) ? 16 : 0));

    float acc[2][8][4];
    #pragma unroll
    for (int mi = 0; mi < 2; mi++)
        #pragma unroll
        for (int ni = 0; ni < 8; ni++)
            #pragma unroll
            for (int e = 0; e < 4; e++) acc[mi][ni][e] = 0.0f;

    uint32_t abase = sb + a_off;
    uint32_t bbase = sb + TILEB + b_off;

    #pragma unroll
    for (int ks = 0; ks < DCOLS / 32; ks++) {       // 8 k-steps of 32 fp8
        uint32_t a0[4], a1[4];
        ldsm4(a0, abase + ks * 32);
        ldsm4(a1, abase + 16 * SKB + ks * 32);
        #pragma unroll
        for (int nb = 0; nb < 4; nb++) {
            uint32_t bf[4];
            ldsm4(bf, bbase + nb * 16 * SKB + ks * 32);
            qmma(acc[0][2 * nb + 0], a0, bf[0], bf[1]);
            qmma(acc[0][2 * nb + 1], a0, bf[2], bf[3]);
            qmma(acc[1][2 * nb + 0], a1, bf[0], bf[1]);
            qmma(acc[1][2 * nb + 1], a1, bf[2], bf[3]);
        }
    }

    // epilogue: g_true = acc/256; exp(min(4*g_true - 4, 0))
    float s = 0.0f;
    #pragma unroll
    for (int mi = 0; mi < 2; mi++)
        #pragma unroll
        for (int ni = 0; ni < 8; ni++)
            #pragma unroll
            for (int e = 0; e < 4; e++) {
                float gv = acc[mi][ni][e];
                float t = fminf(gv * INV_GS - 4.0f, 0.0f);
                s += __expf(t);
            }
    if (bi != bj) s *= 2.0f;
    #pragma unroll
    for (int o = 16; o; o >>= 1) s += __shfl_xor_sync(0xffffffffu, s, o);
    if (lane == 0) sred[wid] = s;
    __syncthreads();
    if (tid == 0) {
        float tot = 0.f;
        #pragma unroll
        for (int i = 0; i < 8; i++) tot += sred[i];
        atomicAdd(&g_acc[1], tot);
    }
}

__global__ void k_final(float* out) {
    float align_loss = g_acc[0] / (float)BPAIRS;
    float S = g_acc[1];
    float uniform_loss = (S - (float)NROWS) / ((float)NROWS * (float)(NROWS - 1));
    out[0] = align_loss + uniform_loss;
}

extern "C" void kernel_launch(void* const* d_in, const int* in_sizes, int n_in,
                              void* d_out, int out_size) {
    const float* A = (const float*)d_in[0];
    const float* B = (const float*)d_in[1];
    float* out = (float*)d_out;

    cudaFuncSetAttribute(k_gram, cudaFuncAttributeMaxDynamicSharedMemorySize, SMEM_TOTAL);

    k_zero<<<1, 1>>>();
    k_norm<<<BPAIRS, 256>>>(A, B);
    const int tiles_1d = NROWS / TM;                       // 64
    const int ntiles = tiles_1d * (tiles_1d + 1) / 2;      // 2080
    k_gram<<<ntiles, 256, SMEM_TOTAL>>>();
    k_final<<<1, 1>>>(out);
}